// round 10
// baseline (speedup 1.0000x reference)
#include <cuda_runtime.h>
#include <cuda_bf16.h>
#include <mma.h>
#include <cstdint>

using namespace nvcuda;

#define NN 262144
#define DD 128
#define KK 512
#define GG 4096
#define TT 10

// output layout (float32, concatenated reference tuple)
#define OFF_CPRE   0
#define OFF_XPRE   (GG * TT)            // counter_pre
#define OFF_YPRE   (2 * GG * TT)
#define OFF_Z      (3 * GG * TT)
#define OFF_PCA    (OFF_Z + (size_t)NN * DD)
#define OFF_PX     (OFF_PCA + (size_t)GG * DD)

#define MARGIN_THRESH 0.01f

#define LDB 136                         // bf16 tile leading dim (elements)
#define LDP 132                         // fp32 score tile leading dim (elements)

#define BTILE_U4 4352                   // one code tile (bh+bl) in uint4s

// smem byte offsets (64-node CTA): [xh|xl][B][c2]; ps overlays B
#define SM_XH   0
#define SM_XL   17408
#define SM_B    34816
#define SM_C2   104448
#define SMEM_TC 106496

__device__ int   g_idx[NN];
__device__ int   g_seg[GG + 1];
__device__ float g_c2[KK];       // fast-path c2
__device__ float g_c2e[KK];      // reference-emulated c2 (sequential fp32, no fma)
__device__ float g_cbT[DD * KK]; // transposed causal codebook for coalesced refine
__device__ int   g_flag[NN];
__device__ int   g_nflag;
__device__ float g_x2f[NN];      // emulated x2 per flagged node (by flag position)
__device__ uint4 g_cbs[4][BTILE_U4];   // pre-split codebook tiles: [bh | bl] blocked layout

// ---------------- cp.async helpers ----------------
__device__ __forceinline__ void cpa16(uint32_t saddr, const void* gptr) {
    asm volatile("cp.async.cg.shared.global [%0], [%1], 16;"
                 :: "r"(saddr), "l"(gptr));
}
__device__ __forceinline__ void cpa_commit() {
    asm volatile("cp.async.commit_group;");
}
__device__ __forceinline__ void cpa_wait0() {
    asm volatile("cp.async.wait_group 0;");
}

// symmetric top-2 merge with first-index tie-break
__device__ __forceinline__ void comb2(float& v1, int& i1, float& v2,
                                      float ov1, int oi1, float ov2) {
    if (ov1 < v1 || (ov1 == v1 && oi1 < i1)) {
        v2 = fminf(v1, ov2);
        v1 = ov1; i1 = oi1;
    } else {
        v2 = fminf(v2, ov1);
    }
}

// ---------------- segment offsets via binary search (batch is sorted) ----------------
__global__ void seg_kernel(const int* __restrict__ bw, int n) {
    int g = blockIdx.x * blockDim.x + threadIdx.x;
    if (g == 0) g_nflag = 0;
    if (g > GG) return;
    bool is64 = (bw[n - 1] == 0) && (bw[n - 3] == 0);
    int lo = 0, hi = n;
    while (lo < hi) {
        int mid = (lo + hi) >> 1;
        int v = is64 ? bw[2 * mid] : bw[mid];
        if (v < g) lo = mid + 1; else hi = mid;
    }
    g_seg[g] = lo;
}

// ---------------- fast c2 + emulated c2 + transpose, fused ----------------
__global__ void prep_kernel(const float* __restrict__ cc) {
    int k = blockIdx.x * 8 + (threadIdx.x >> 5);
    int lane = threadIdx.x & 31;
    float v[4];
    float s = 0.f;
#pragma unroll
    for (int j = 0; j < 4; ++j) {
        v[j] = cc[k * DD + lane + 32 * j];
        s = fmaf(v[j], v[j], s);
        g_cbT[(lane + 32 * j) * KK + k] = v[j];
    }
#pragma unroll
    for (int o = 16; o; o >>= 1) s += __shfl_xor_sync(0xffffffffu, s, o);
    if (lane == 0) g_c2[k] = s;
    if (lane == 0) {
        const float* r = cc + (size_t)k * DD;
        float acc = 0.f;
        for (int d = 0; d < DD; ++d)
            acc = __fadd_rn(acc, __fmul_rn(r[d], r[d]));
        g_c2e[k] = acc;
    }
}

// split one 8-float chunk to packed bf16 hi/lo uint4s
__device__ __forceinline__ void split8(const float* f, uint4& H, uint4& L) {
    uint32_t hp[4], lp[4];
#pragma unroll
    for (int j = 0; j < 4; ++j) {
        __nv_bfloat16 h0 = __float2bfloat16(f[2 * j]);
        __nv_bfloat16 h1 = __float2bfloat16(f[2 * j + 1]);
        __nv_bfloat16 l0 = __float2bfloat16(f[2 * j]     - __bfloat162float(h0));
        __nv_bfloat16 l1 = __float2bfloat16(f[2 * j + 1] - __bfloat162float(h1));
        hp[j] = ((uint32_t)__bfloat16_as_ushort(h1) << 16) | __bfloat16_as_ushort(h0);
        lp[j] = ((uint32_t)__bfloat16_as_ushort(l1) << 16) | __bfloat16_as_ushort(l0);
    }
    H = make_uint4(hp[0], hp[1], hp[2], hp[3]);
    L = make_uint4(lp[0], lp[1], lp[2], lp[3]);
}

// ---------------- pre-split codebook tiles to gmem (blocked smem layout) ----------
__global__ __launch_bounds__(256) void prep_split_kernel(const float* __restrict__ cb) {
    const int kt = blockIdx.x;           // 4 tiles
    const int tid = threadIdx.x;
#pragma unroll
    for (int it = 0; it < 8; ++it) {
        int idx = it * 256 + tid;        // 0..2047
        int row = idx >> 4, ch = idx & 15;
        float f[8];
        const float4* p = (const float4*)(cb + (size_t)(kt * 128 + row) * DD) + ch * 2;
        float4 v0 = p[0], v1 = p[1];
        f[0]=v0.x; f[1]=v0.y; f[2]=v0.z; f[3]=v0.w; f[4]=v1.x; f[5]=v1.y; f[6]=v1.z; f[7]=v1.w;
        uint4 H, L;
        split8(f, H, L);
        int u4 = row * 17 + ch;          // 272B rows = 17 uint4
        g_cbs[kt][u4] = H;
        g_cbs[kt][2176 + u4] = L;
    }
}

// ---------------- HMMA argmin: 64 nodes/CTA, 2 CTA/SM, split-bf16 3-pass -------------
__global__ __launch_bounds__(256, 2) void argmin_tc(
    const float* __restrict__ x)
{
    extern __shared__ char smem[];
    __nv_bfloat16* xh  = (__nv_bfloat16*)(smem + SM_XH);
    __nv_bfloat16* xl  = (__nv_bfloat16*)(smem + SM_XL);
    __nv_bfloat16* bh  = (__nv_bfloat16*)(smem + SM_B);
    __nv_bfloat16* bl  = (__nv_bfloat16*)(smem + SM_B + 34816);
    float*         ps  = (float*)(smem + SM_B);       // overlays B after mma
    float*         c2s = (float*)(smem + SM_C2);

    const int tid = threadIdx.x;
    const int wid = tid >> 5;
    const int wm  = wid & 1;             // node block: 32*wm..
    const int wn  = wid >> 1;            // code block: 32*wn..
    const int nbase = blockIdx.x * 64;

    const uint32_t sb = (uint32_t)__cvta_generic_to_shared(smem + SM_B);

    // prefetch tile 0 while converting X
    {
        const uint4* src = g_cbs[0];
#pragma unroll
        for (int i = 0; i < 17; ++i) {
            int idx = tid + 256 * i;
            cpa16(sb + idx * 16, src + idx);
        }
        cpa_commit();
    }

    // fill X (64 rows) bf16 hi/lo
#pragma unroll
    for (int it = 0; it < 4; ++it) {
        int idx = it * 256 + tid;        // 0..1023
        int row = idx >> 4, ch = idx & 15;
        const float4* p = (const float4*)(x + (size_t)(nbase + row) * DD) + ch * 2;
        float4 v0 = p[0], v1 = p[1];
        float f[8] = {v0.x, v0.y, v0.z, v0.w, v1.x, v1.y, v1.z, v1.w};
        uint4 H, L;
        split8(f, H, L);
        int eo = row * LDB + ch * 8;
        *(uint4*)((char*)xh + 2 * eo) = H;
        *(uint4*)((char*)xl + 2 * eo) = L;
    }
    for (int k = tid; k < KK; k += 256) c2s[k] = g_c2[k];

    // scan ownership: 4 threads per node, one 32-code quarter each
    const int node = tid >> 2;
    const int q4   = tid & 3;

    float bestv = 3.4e38f, bestv2 = 3.4e38f;
    int   besti = 0x7fffffff;

    for (int kt = 0; kt < 4; ++kt) {
        if (kt > 0) {
            __syncthreads();             // scan of kt-1 done; safe to overwrite ps/B
            const uint4* src = g_cbs[kt];
#pragma unroll
            for (int i = 0; i < 17; ++i) {
                int idx = tid + 256 * i;
                cpa16(sb + idx * 16, src + idx);
            }
            cpa_commit();
        }
        cpa_wait0();
        __syncthreads();                 // B tile kt ready (X also ready on kt=0)

        wmma::fragment<wmma::accumulator, 16, 16, 16, float> acc[2][2];
#pragma unroll
        for (int i = 0; i < 2; ++i)
#pragma unroll
            for (int j = 0; j < 2; ++j) wmma::fill_fragment(acc[i][j], 0.f);

#pragma unroll
        for (int kk = 0; kk < 8; ++kk) {
            const int k0 = kk * 16;
            wmma::fragment<wmma::matrix_a, 16, 16, 16, __nv_bfloat16, wmma::row_major> ah[2], al[2];
            wmma::fragment<wmma::matrix_b, 16, 16, 16, __nv_bfloat16, wmma::col_major> bhf[2], blf[2];
#pragma unroll
            for (int i = 0; i < 2; ++i) {
                wmma::load_matrix_sync(ah[i], xh + (wm * 32 + i * 16) * LDB + k0, LDB);
                wmma::load_matrix_sync(al[i], xl + (wm * 32 + i * 16) * LDB + k0, LDB);
            }
#pragma unroll
            for (int j = 0; j < 2; ++j) {
                wmma::load_matrix_sync(bhf[j], bh + (wn * 32 + j * 16) * LDB + k0, LDB);
                wmma::load_matrix_sync(blf[j], bl + (wn * 32 + j * 16) * LDB + k0, LDB);
            }
#pragma unroll
            for (int i = 0; i < 2; ++i)
#pragma unroll
                for (int j = 0; j < 2; ++j) {
                    wmma::mma_sync(acc[i][j], ah[i], bhf[j], acc[i][j]);
                    wmma::mma_sync(acc[i][j], ah[i], blf[j], acc[i][j]);
                    wmma::mma_sync(acc[i][j], al[i], bhf[j], acc[i][j]);
                }
        }
        __syncthreads();                 // all warps done reading bh/bl

#pragma unroll
        for (int i = 0; i < 2; ++i)
#pragma unroll
            for (int j = 0; j < 2; ++j)
                wmma::store_matrix_sync(
                    ps + (wm * 32 + i * 16) * LDP + wn * 32 + j * 16,
                    acc[i][j], LDP, wmma::mem_row_major);
        __syncthreads();

        // scan: each thread scans its 32-code quarter of its node (k ascending)
        {
            const float4* row = (const float4*)(ps + node * LDP) + q4 * 8;
#pragma unroll
            for (int q = 0; q < 8; ++q) {
                float4 v = row[q];
                float d4[4] = {v.x, v.y, v.z, v.w};
#pragma unroll
                for (int u = 0; u < 4; ++u) {
                    int k = kt * 128 + q4 * 32 + 4 * q + u;
                    float s = fmaf(-2.f, d4[u], c2s[k]);
                    if (s < bestv)       { bestv2 = bestv; bestv = s; besti = k; }
                    else if (s < bestv2) { bestv2 = s; }
                }
            }
        }
    }

    // merge top-2 across the 4 quarter-threads of each node (same warp)
#pragma unroll
    for (int off = 1; off <= 2; off <<= 1) {
        float ov1 = __shfl_xor_sync(0xffffffffu, bestv,  off);
        float ov2 = __shfl_xor_sync(0xffffffffu, bestv2, off);
        int   oi1 = __shfl_xor_sync(0xffffffffu, besti,  off);
        comb2(bestv, besti, bestv2, ov1, oi1, ov2);
    }

    if (q4 == 0) {
        int gn = nbase + node;
        g_idx[gn] = besti;
        if (bestv2 - bestv < MARGIN_THRESH) {
            int pos = atomicAdd(&g_nflag, 1);
            g_flag[pos] = gn;
        }
    }
}

// ---------------- emulated x2 for flagged nodes (parallel, one thread/node) ----------
__global__ void x2pre_kernel(const float* __restrict__ x) {
    int nf = g_nflag;
    for (int j = blockIdx.x * 128 + threadIdx.x; j < nf; j += gridDim.x * 128) {
        const float* r = x + (size_t)g_flag[j] * DD;
        float acc = 0.f;
        for (int d = 0; d < DD; ++d)
            acc = __fadd_rn(acc, __fmul_rn(r[d], r[d]));
        g_x2f[j] = acc;
    }
}

// ---------------- near-tie refine: bit-emulate the reference's fp32 arithmetic --------
__global__ __launch_bounds__(128) void refine_kernel(const float* __restrict__ x)
{
    __shared__ float xsh[DD];
    __shared__ float bvs[128];
    __shared__ int   bis[128];
    const int tid = threadIdx.x;
    const int nflag = g_nflag;

    for (int f = blockIdx.x; f < nflag; f += gridDim.x) {
        int node = g_flag[f];
        xsh[tid] = x[(size_t)node * DD + tid];
        __syncthreads();
        float x2 = g_x2f[f];

        float bestv = 3.4e38f; int besti = 0x7fffffff;
#pragma unroll
        for (int j = 0; j < 4; ++j) {
            int k = j * 128 + tid;               // lane-consecutive k: coalesced
            float dot = 0.f;
            for (int d = 0; d < DD; ++d)
                dot = __fmaf_rn(xsh[d], g_cbT[d * KK + k], dot);
            float s = __fsub_rn(__fadd_rn(x2, g_c2e[k]), __fmul_rn(2.f, dot));
            if (s < bestv || (s == bestv && k < besti)) { bestv = s; besti = k; }
        }
        bvs[tid] = bestv; bis[tid] = besti;
        __syncthreads();
        for (int st = 64; st > 0; st >>= 1) {
            if (tid < st) {
                float v2 = bvs[tid + st]; int k2 = bis[tid + st];
                if (v2 < bvs[tid] || (v2 == bvs[tid] && k2 < bis[tid])) {
                    bvs[tid] = v2; bis[tid] = k2;
                }
            }
            __syncthreads();
        }
        if (tid == 0) g_idx[node] = bis[0];
        __syncthreads();
    }
}

// ---------------- z_nodes gather: out_z[i] = codebook[idx[i]] ----------------
__global__ void gather_kernel(const float* __restrict__ cb, float* __restrict__ outz) {
    int gid = blockIdx.x * 256 + threadIdx.x;   // over N*32 float4s
    int i = gid >> 5, q = gid & 31;
    int k = g_idx[i];
    ((float4*)outz)[(size_t)i * 32 + q] = ((const float4*)cb)[(size_t)k * 32 + q];
}

// ---------------- per-graph pooling + tiny matmuls (128 threads, 4-warp split) -------
__global__ __launch_bounds__(128) void pool_kernel(
    const float* __restrict__ x, const float* __restrict__ causal,
    const float* __restrict__ counter, const float* __restrict__ fcw,
    const float* __restrict__ fcb, float* __restrict__ out)
{
    __shared__ float part[4][3][DD];   // per-warp partial sums
    __shared__ float pv[3][DD];
    __shared__ float wsh[TT * DD];
    const int g = blockIdx.x, tid = threadIdx.x;
    const int w = tid >> 5, t = tid & 31;

    for (int j = tid; j < TT * DD; j += 128) wsh[j] = fcw[j];

    const float4* x4 = (const float4*)x;
    const float4* a4 = (const float4*)causal;
    const float4* c4 = (const float4*)counter;

    int s = g_seg[g], e = g_seg[g + 1];
    float4 sx = {0,0,0,0}, sa = {0,0,0,0}, sc = {0,0,0,0};
#pragma unroll 2
    for (int i = s + w; i < e; i += 4) {
        int k = g_idx[i];
        float4 vx = x4[(size_t)i * 32 + t];
        float4 va = a4[(size_t)k * 32 + t];
        float4 vc = c4[(size_t)k * 32 + t];
        sx.x += vx.x; sx.y += vx.y; sx.z += vx.z; sx.w += vx.w;
        sa.x += va.x; sa.y += va.y; sa.z += va.z; sa.w += va.w;
        sc.x += vc.x; sc.y += vc.y; sc.z += vc.z; sc.w += vc.w;
    }
    ((float4*)part[w][0])[t] = sx;
    ((float4*)part[w][1])[t] = sa;
    ((float4*)part[w][2])[t] = sc;
    __syncthreads();

    float fx = (part[0][0][tid] + part[1][0][tid]) + (part[2][0][tid] + part[3][0][tid]);
    float fa = (part[0][1][tid] + part[1][1][tid]) + (part[2][1][tid] + part[3][1][tid]);
    float fc = (part[0][2][tid] + part[1][2][tid]) + (part[2][2][tid] + part[3][2][tid]);

    float cnt = (float)(e - s);
    float inv = 1.f / fmaxf(cnt, 1.f);
    float px  = fx * inv;
    float pca = (fx + fa) * inv;
    float pco = fc * inv;

    out[OFF_PCA + (size_t)g * DD + tid] = pca;
    out[OFF_PX  + (size_t)g * DD + tid] = px;

    pv[0][tid] = pca; pv[1][tid] = pco; pv[2][tid] = px;
    __syncthreads();

    if (tid < 3 * TT) {
        int v = tid / TT, tk = tid % TT;
        float acc = fcb[tk];
#pragma unroll 8
        for (int q = 0; q < DD; ++q) acc = fmaf(pv[v][q], wsh[tk * DD + q], acc);
        out[(size_t)v * (GG * TT) + g * TT + tk] = acc;
    }
}

extern "C" void kernel_launch(void* const* d_in, const int* in_sizes, int n_in,
                              void* d_out, int out_size) {
    const float* x        = (const float*)d_in[0];
    const int*   batch    = (const int*)  d_in[1];
    const float* codebook = (const float*)d_in[2];
    const float* causal   = (const float*)d_in[3];
    const float* counter  = (const float*)d_in[4];
    const float* fcw      = (const float*)d_in[5];
    const float* fcb      = (const float*)d_in[6];
    float* out = (float*)d_out;

    cudaFuncSetAttribute(argmin_tc,
                         cudaFuncAttributeMaxDynamicSharedMemorySize, SMEM_TC);

    seg_kernel<<<(GG + 1 + 255) / 256, 256>>>(batch, NN);
    prep_kernel<<<KK / 8, 256>>>(causal);
    prep_split_kernel<<<4, 256>>>(causal);
    argmin_tc<<<NN / 64, 256, SMEM_TC>>>(x);
    x2pre_kernel<<<256, 128>>>(x);
    refine_kernel<<<256, 128>>>(x);
    gather_kernel<<<(NN * 32) / 256, 256>>>(codebook, out + OFF_Z);
    pool_kernel<<<GG, 128>>>(x, causal, counter, fcw, fcb, out);
}

// round 11
// speedup vs baseline: 1.1544x; 1.1544x over previous
#include <cuda_runtime.h>
#include <cuda_bf16.h>
#include <mma.h>
#include <cstdint>

using namespace nvcuda;

#define NN 262144
#define DD 128
#define KK 512
#define GG 4096
#define TT 10

// output layout (float32, concatenated reference tuple)
#define OFF_CPRE   0
#define OFF_XPRE   (GG * TT)            // counter_pre
#define OFF_YPRE   (2 * GG * TT)
#define OFF_Z      (3 * GG * TT)
#define OFF_PCA    (OFF_Z + (size_t)NN * DD)
#define OFF_PX     (OFF_PCA + (size_t)GG * DD)

#define MARGIN_THRESH 0.01f

#define LDB 136                         // bf16 tile leading dim (elements)
#define LDP 132                         // fp32 score tile leading dim (elements)

#define BTILE_U4 4352                   // one code tile (bh+bl) in uint4s
#define BUFSZ    69632                  // bytes per B buffer (bh+bl)

// smem byte offsets (128-node CTA): [xh|xl][B0][B1][c2]; ps overlays consumed B buffer
#define SM_XH   0
#define SM_XL   34816
#define SM_B0   69632
#define SM_B1   139264
#define SM_C2   208896
#define SMEM_TC 210944

__device__ int   g_idx[NN];
__device__ int   g_seg[GG + 1];
__device__ float g_c2[KK];       // fast-path c2
__device__ float g_c2e[KK];      // reference-emulated c2 (sequential fp32, no fma)
__device__ float g_cbT[DD * KK]; // transposed causal codebook for coalesced refine
__device__ int   g_flag[NN];
__device__ int   g_nflag;
__device__ float g_x2f[NN];      // emulated x2 per flagged node (by flag position)
__device__ uint4 g_cbs[4][BTILE_U4];   // pre-split codebook tiles: [bh | bl] blocked layout

// ---------------- cp.async helpers ----------------
__device__ __forceinline__ void cpa16(uint32_t saddr, const void* gptr) {
    asm volatile("cp.async.cg.shared.global [%0], [%1], 16;"
                 :: "r"(saddr), "l"(gptr));
}
__device__ __forceinline__ void cpa_commit() {
    asm volatile("cp.async.commit_group;");
}
__device__ __forceinline__ void cpa_wait0() {
    asm volatile("cp.async.wait_group 0;");
}
__device__ __forceinline__ void cpa_wait1() {
    asm volatile("cp.async.wait_group 1;");
}

// symmetric top-2 merge with first-index tie-break
__device__ __forceinline__ void comb2(float& v1, int& i1, float& v2,
                                      float ov1, int oi1, float ov2) {
    if (ov1 < v1 || (ov1 == v1 && oi1 < i1)) {
        v2 = fminf(v1, ov2);
        v1 = ov1; i1 = oi1;
    } else {
        v2 = fminf(v2, ov1);
    }
}

// ---------------- segment offsets via binary search (batch is sorted) ----------------
__global__ void seg_kernel(const int* __restrict__ bw, int n) {
    int g = blockIdx.x * blockDim.x + threadIdx.x;
    if (g == 0) g_nflag = 0;
    if (g > GG) return;
    bool is64 = (bw[n - 1] == 0) && (bw[n - 3] == 0);
    int lo = 0, hi = n;
    while (lo < hi) {
        int mid = (lo + hi) >> 1;
        int v = is64 ? bw[2 * mid] : bw[mid];
        if (v < g) lo = mid + 1; else hi = mid;
    }
    g_seg[g] = lo;
}

// ---------------- fast c2 + emulated c2 + transpose, fused ----------------
__global__ void prep_kernel(const float* __restrict__ cc) {
    int k = blockIdx.x * 8 + (threadIdx.x >> 5);
    int lane = threadIdx.x & 31;
    float v[4];
    float s = 0.f;
#pragma unroll
    for (int j = 0; j < 4; ++j) {
        v[j] = cc[k * DD + lane + 32 * j];
        s = fmaf(v[j], v[j], s);
        g_cbT[(lane + 32 * j) * KK + k] = v[j];
    }
#pragma unroll
    for (int o = 16; o; o >>= 1) s += __shfl_xor_sync(0xffffffffu, s, o);
    if (lane == 0) g_c2[k] = s;
    if (lane == 0) {
        const float* r = cc + (size_t)k * DD;
        float acc = 0.f;
        for (int d = 0; d < DD; ++d)
            acc = __fadd_rn(acc, __fmul_rn(r[d], r[d]));
        g_c2e[k] = acc;
    }
}

// split one 8-float chunk to packed bf16 hi/lo uint4s
__device__ __forceinline__ void split8(const float* f, uint4& H, uint4& L) {
    uint32_t hp[4], lp[4];
#pragma unroll
    for (int j = 0; j < 4; ++j) {
        __nv_bfloat16 h0 = __float2bfloat16(f[2 * j]);
        __nv_bfloat16 h1 = __float2bfloat16(f[2 * j + 1]);
        __nv_bfloat16 l0 = __float2bfloat16(f[2 * j]     - __bfloat162float(h0));
        __nv_bfloat16 l1 = __float2bfloat16(f[2 * j + 1] - __bfloat162float(h1));
        hp[j] = ((uint32_t)__bfloat16_as_ushort(h1) << 16) | __bfloat16_as_ushort(h0);
        lp[j] = ((uint32_t)__bfloat16_as_ushort(l1) << 16) | __bfloat16_as_ushort(l0);
    }
    H = make_uint4(hp[0], hp[1], hp[2], hp[3]);
    L = make_uint4(lp[0], lp[1], lp[2], lp[3]);
}

// ---------------- pre-split codebook tiles to gmem (blocked smem layout) ----------
__global__ __launch_bounds__(256) void prep_split_kernel(const float* __restrict__ cb) {
    const int kt = blockIdx.x;           // 4 tiles
    const int tid = threadIdx.x;
#pragma unroll
    for (int it = 0; it < 8; ++it) {
        int idx = it * 256 + tid;        // 0..2047
        int row = idx >> 4, ch = idx & 15;
        float f[8];
        const float4* p = (const float4*)(cb + (size_t)(kt * 128 + row) * DD) + ch * 2;
        float4 v0 = p[0], v1 = p[1];
        f[0]=v0.x; f[1]=v0.y; f[2]=v0.z; f[3]=v0.w; f[4]=v1.x; f[5]=v1.y; f[6]=v1.z; f[7]=v1.w;
        uint4 H, L;
        split8(f, H, L);
        int u4 = row * 17 + ch;          // 272B rows = 17 uint4
        g_cbs[kt][u4] = H;
        g_cbs[kt][2176 + u4] = L;
    }
}

// ---------------- HMMA argmin: 128 nodes/CTA, warp-local scan, deep prefetch ---------
__global__ __launch_bounds__(256) void argmin_tc(
    const float* __restrict__ x)
{
    extern __shared__ char smem[];
    __nv_bfloat16* xh  = (__nv_bfloat16*)(smem + SM_XH);
    __nv_bfloat16* xl  = (__nv_bfloat16*)(smem + SM_XL);
    float*         c2s = (float*)(smem + SM_C2);

    const int tid  = threadIdx.x;
    const int wid  = tid >> 5;
    const int lane = tid & 31;
    const int wm   = wid & 3;            // node block: rows 32*wm..
    const int wn   = wid >> 2;           // code block: cols 64*wn..
    const int nbase = blockIdx.x * 128;

    const uint32_t sb0 = (uint32_t)__cvta_generic_to_shared(smem + SM_B0);
    const uint32_t sb1 = (uint32_t)__cvta_generic_to_shared(smem + SM_B1);

    // prefetch tiles 0 and 1 (two groups in flight) while converting X
#pragma unroll
    for (int b = 0; b < 2; ++b) {
        const uint4* src = g_cbs[b];
        uint32_t dst = b ? sb1 : sb0;
#pragma unroll
        for (int i = 0; i < 17; ++i) {
            int idx = tid + 256 * i;
            cpa16(dst + idx * 16, src + idx);
        }
        cpa_commit();
    }

    // fill X (128 rows) bf16 hi/lo
#pragma unroll
    for (int it = 0; it < 8; ++it) {
        int idx = it * 256 + tid;        // 0..2047
        int row = idx >> 4, ch = idx & 15;
        const float4* p = (const float4*)(x + (size_t)(nbase + row) * DD) + ch * 2;
        float4 v0 = p[0], v1 = p[1];
        float f[8] = {v0.x, v0.y, v0.z, v0.w, v1.x, v1.y, v1.z, v1.w};
        uint4 H, L;
        split8(f, H, L);
        int eo = row * LDB + ch * 8;
        *(uint4*)((char*)xh + 2 * eo) = H;
        *(uint4*)((char*)xl + 2 * eo) = L;
    }
    for (int k = tid; k < KK; k += 256) c2s[k] = g_c2[k];

    float bestv = 3.4e38f, bestv2 = 3.4e38f;
    int   besti = 0x7fffffff;

    for (int kt = 0; kt < 4; ++kt) {
        if (kt > 0) {
            __syncthreads();             // scans of kt-1 (ps in buf((kt-1)&1)) complete
            if (kt <= 2) {               // prefetch tile kt+1 into buf((kt+1)&1)
                const uint4* src = g_cbs[kt + 1];
                uint32_t dst = ((kt + 1) & 1) ? sb1 : sb0;
#pragma unroll
                for (int i = 0; i < 17; ++i) {
                    int idx = tid + 256 * i;
                    cpa16(dst + idx * 16, src + idx);
                }
                cpa_commit();
            }
        }
        if (kt < 3) cpa_wait1(); else cpa_wait0();
        __syncthreads();                 // B(kt) visible to all (X too on kt=0)

        char* bbase = smem + ((kt & 1) ? SM_B1 : SM_B0);
        __nv_bfloat16* bh = (__nv_bfloat16*)bbase;
        __nv_bfloat16* bl = (__nv_bfloat16*)(bbase + 34816);
        float*         ps = (float*)bbase;

        wmma::fragment<wmma::accumulator, 16, 16, 16, float> acc[2][4];
#pragma unroll
        for (int i = 0; i < 2; ++i)
#pragma unroll
            for (int j = 0; j < 4; ++j) wmma::fill_fragment(acc[i][j], 0.f);

#pragma unroll
        for (int kk = 0; kk < 8; ++kk) {
            const int k0 = kk * 16;
            wmma::fragment<wmma::matrix_a, 16, 16, 16, __nv_bfloat16, wmma::row_major> ah[2], al[2];
            wmma::fragment<wmma::matrix_b, 16, 16, 16, __nv_bfloat16, wmma::col_major> bhf[4], blf[4];
#pragma unroll
            for (int i = 0; i < 2; ++i) {
                wmma::load_matrix_sync(ah[i], xh + (wm * 32 + i * 16) * LDB + k0, LDB);
                wmma::load_matrix_sync(al[i], xl + (wm * 32 + i * 16) * LDB + k0, LDB);
            }
#pragma unroll
            for (int j = 0; j < 4; ++j) {
                wmma::load_matrix_sync(bhf[j], bh + (wn * 64 + j * 16) * LDB + k0, LDB);
                wmma::load_matrix_sync(blf[j], bl + (wn * 64 + j * 16) * LDB + k0, LDB);
            }
#pragma unroll
            for (int i = 0; i < 2; ++i)
#pragma unroll
                for (int j = 0; j < 4; ++j) {
                    wmma::mma_sync(acc[i][j], ah[i], bhf[j], acc[i][j]);
                    wmma::mma_sync(acc[i][j], ah[i], blf[j], acc[i][j]);
                    wmma::mma_sync(acc[i][j], al[i], bhf[j], acc[i][j]);
                }
        }
        __syncthreads();                 // all warps done reading bh/bl

        // warp-local store into this warp's disjoint ps region
#pragma unroll
        for (int i = 0; i < 2; ++i)
#pragma unroll
            for (int j = 0; j < 4; ++j)
                wmma::store_matrix_sync(
                    ps + (wm * 32 + i * 16) * LDP + wn * 64 + j * 16,
                    acc[i][j], LDP, wmma::mem_row_major);
        __syncwarp();                    // warp-local visibility (no block barrier)

        // warp-local scan: thread=row (node wm*32+lane), 64 cols of this warp's half
        {
            const float4* row = (const float4*)(ps + (wm * 32 + lane) * LDP) + wn * 16;
#pragma unroll
            for (int q = 0; q < 16; ++q) {
                float4 v = row[q];
                float d4[4] = {v.x, v.y, v.z, v.w};
#pragma unroll
                for (int u = 0; u < 4; ++u) {
                    int k = kt * 128 + wn * 64 + 4 * q + u;
                    float s = fmaf(-2.f, d4[u], c2s[k]);
                    if (s < bestv)       { bestv2 = bestv; bestv = s; besti = k; }
                    else if (s < bestv2) { bestv2 = s; }
                }
            }
        }
    }

    // final cross-half merge: X region is dead after last mma (post-mma sync passed)
    __syncthreads();
    float* mv1 = (float*)(smem + SM_XH);            // [8][32]
    float* mv2 = mv1 + 256;                          // [8][32]
    int*   mi1 = (int*)(mv2 + 256);                  // [8][32]
    mv1[wid * 32 + lane] = bestv;
    mv2[wid * 32 + lane] = bestv2;
    mi1[wid * 32 + lane] = besti;
    __syncthreads();

    if (tid < 128) {
        int bm = tid >> 5, t = tid & 31;
        float v1 = mv1[bm * 32 + t], v2 = mv2[bm * 32 + t];
        int   i1 = mi1[bm * 32 + t];
        comb2(v1, i1, v2,
              mv1[(bm + 4) * 32 + t], mi1[(bm + 4) * 32 + t], mv2[(bm + 4) * 32 + t]);
        int gn = nbase + bm * 32 + t;
        g_idx[gn] = i1;
        if (v2 - v1 < MARGIN_THRESH) {
            int pos = atomicAdd(&g_nflag, 1);
            g_flag[pos] = gn;
        }
    }
}

// ---------------- emulated x2 for flagged nodes (parallel, one thread/node) ----------
__global__ void x2pre_kernel(const float* __restrict__ x) {
    int nf = g_nflag;
    for (int j = blockIdx.x * 128 + threadIdx.x; j < nf; j += gridDim.x * 128) {
        const float* r = x + (size_t)g_flag[j] * DD;
        float acc = 0.f;
        for (int d = 0; d < DD; ++d)
            acc = __fadd_rn(acc, __fmul_rn(r[d], r[d]));
        g_x2f[j] = acc;
    }
}

// ---------------- near-tie refine: bit-emulate the reference's fp32 arithmetic --------
__global__ __launch_bounds__(128) void refine_kernel(const float* __restrict__ x)
{
    __shared__ float xsh[DD];
    __shared__ float bvs[128];
    __shared__ int   bis[128];
    const int tid = threadIdx.x;
    const int nflag = g_nflag;

    for (int f = blockIdx.x; f < nflag; f += gridDim.x) {
        int node = g_flag[f];
        xsh[tid] = x[(size_t)node * DD + tid];
        __syncthreads();
        float x2 = g_x2f[f];

        float bestv = 3.4e38f; int besti = 0x7fffffff;
#pragma unroll
        for (int j = 0; j < 4; ++j) {
            int k = j * 128 + tid;               // lane-consecutive k: coalesced
            float dot = 0.f;
            for (int d = 0; d < DD; ++d)
                dot = __fmaf_rn(xsh[d], g_cbT[d * KK + k], dot);
            float s = __fsub_rn(__fadd_rn(x2, g_c2e[k]), __fmul_rn(2.f, dot));
            if (s < bestv || (s == bestv && k < besti)) { bestv = s; besti = k; }
        }
        bvs[tid] = bestv; bis[tid] = besti;
        __syncthreads();
        for (int st = 64; st > 0; st >>= 1) {
            if (tid < st) {
                float v2 = bvs[tid + st]; int k2 = bis[tid + st];
                if (v2 < bvs[tid] || (v2 == bvs[tid] && k2 < bis[tid])) {
                    bvs[tid] = v2; bis[tid] = k2;
                }
            }
            __syncthreads();
        }
        if (tid == 0) g_idx[node] = bis[0];
        __syncthreads();
    }
}

// ---------------- z_nodes gather: out_z[i] = codebook[idx[i]] ----------------
__global__ void gather_kernel(const float* __restrict__ cb, float* __restrict__ outz) {
    int gid = blockIdx.x * 256 + threadIdx.x;   // over N*32 float4s
    int i = gid >> 5, q = gid & 31;
    int k = g_idx[i];
    ((float4*)outz)[(size_t)i * 32 + q] = ((const float4*)cb)[(size_t)k * 32 + q];
}

// ---------------- per-graph pooling + tiny matmuls (128 threads, 4-warp split) -------
__global__ __launch_bounds__(128) void pool_kernel(
    const float* __restrict__ x, const float* __restrict__ causal,
    const float* __restrict__ counter, const float* __restrict__ fcw,
    const float* __restrict__ fcb, float* __restrict__ out)
{
    __shared__ float part[4][3][DD];   // per-warp partial sums
    __shared__ float pv[3][DD];
    __shared__ float wsh[TT * DD];
    const int g = blockIdx.x, tid = threadIdx.x;
    const int w = tid >> 5, t = tid & 31;

    for (int j = tid; j < TT * DD; j += 128) wsh[j] = fcw[j];

    const float4* x4 = (const float4*)x;
    const float4* a4 = (const float4*)causal;
    const float4* c4 = (const float4*)counter;

    int s = g_seg[g], e = g_seg[g + 1];
    float4 sx = {0,0,0,0}, sa = {0,0,0,0}, sc = {0,0,0,0};
#pragma unroll 2
    for (int i = s + w; i < e; i += 4) {
        int k = g_idx[i];
        float4 vx = x4[(size_t)i * 32 + t];
        float4 va = a4[(size_t)k * 32 + t];
        float4 vc = c4[(size_t)k * 32 + t];
        sx.x += vx.x; sx.y += vx.y; sx.z += vx.z; sx.w += vx.w;
        sa.x += va.x; sa.y += va.y; sa.z += va.z; sa.w += va.w;
        sc.x += vc.x; sc.y += vc.y; sc.z += vc.z; sc.w += vc.w;
    }
    ((float4*)part[w][0])[t] = sx;
    ((float4*)part[w][1])[t] = sa;
    ((float4*)part[w][2])[t] = sc;
    __syncthreads();

    float fx = (part[0][0][tid] + part[1][0][tid]) + (part[2][0][tid] + part[3][0][tid]);
    float fa = (part[0][1][tid] + part[1][1][tid]) + (part[2][1][tid] + part[3][1][tid]);
    float fc = (part[0][2][tid] + part[1][2][tid]) + (part[2][2][tid] + part[3][2][tid]);

    float cnt = (float)(e - s);
    float inv = 1.f / fmaxf(cnt, 1.f);
    float px  = fx * inv;
    float pca = (fx + fa) * inv;
    float pco = fc * inv;

    out[OFF_PCA + (size_t)g * DD + tid] = pca;
    out[OFF_PX  + (size_t)g * DD + tid] = px;

    pv[0][tid] = pca; pv[1][tid] = pco; pv[2][tid] = px;
    __syncthreads();

    if (tid < 3 * TT) {
        int v = tid / TT, tk = tid % TT;
        float acc = fcb[tk];
#pragma unroll 8
        for (int q = 0; q < DD; ++q) acc = fmaf(pv[v][q], wsh[tk * DD + q], acc);
        out[(size_t)v * (GG * TT) + g * TT + tk] = acc;
    }
}

extern "C" void kernel_launch(void* const* d_in, const int* in_sizes, int n_in,
                              void* d_out, int out_size) {
    const float* x        = (const float*)d_in[0];
    const int*   batch    = (const int*)  d_in[1];
    const float* codebook = (const float*)d_in[2];
    const float* causal   = (const float*)d_in[3];
    const float* counter  = (const float*)d_in[4];
    const float* fcw      = (const float*)d_in[5];
    const float* fcb      = (const float*)d_in[6];
    float* out = (float*)d_out;

    cudaFuncSetAttribute(argmin_tc,
                         cudaFuncAttributeMaxDynamicSharedMemorySize, SMEM_TC);

    seg_kernel<<<(GG + 1 + 255) / 256, 256>>>(batch, NN);
    prep_kernel<<<KK / 8, 256>>>(causal);
    prep_split_kernel<<<4, 256>>>(causal);
    argmin_tc<<<NN / 128, 256, SMEM_TC>>>(x);
    x2pre_kernel<<<256, 128>>>(x);
    refine_kernel<<<256, 128>>>(x);
    gather_kernel<<<(NN * 32) / 256, 256>>>(codebook, out + OFF_Z);
    pool_kernel<<<GG, 128>>>(x, causal, counter, fcw, fcb, out);
}